// round 5
// baseline (speedup 1.0000x reference)
#include <cuda_runtime.h>
#include <cuda_bf16.h>

#define NBINS 36
#define PS    32
#define SROW  36   // padded smem row stride (16B-aligned rows, conflict shift)

__global__ __launch_bounds__(256, 8)
void orientation_kernel(const float* __restrict__ x,
                        const float* __restrict__ smooth_w,
                        const float* __restrict__ gk,
                        float* __restrict__ out)
{
    __shared__ __align__(16) float sp[PS * SROW];
    __shared__ float hist[NBINS];
    __shared__ float smv[NBINS];

    const int t = threadIdx.x;
    const int b = blockIdx.x;

    // ---- stage patch: 1 LDG.128 + 1 STS.128 per thread ----
    const float4* xv = reinterpret_cast<const float4*>(x + (size_t)b * (PS * PS));
    float4 v = xv[t];
    const int row = t >> 3;           // 0..31
    const int c0  = (t & 7) * 4;      // 0,4,...,28
    *reinterpret_cast<float4*>(&sp[row * SROW + c0]) = v;
    if (t < NBINS) hist[t] = 0.0f;
    __syncthreads();

    // ---- replicate-padded neighbors ----
    const int rup = (row == 0)      ? 0      : row - 1;
    const int rdn = (row == PS - 1) ? PS - 1 : row + 1;
    float4 up = *reinterpret_cast<const float4*>(&sp[rup * SROW + c0]);
    float4 dn = *reinterpret_cast<const float4*>(&sp[rdn * SROW + c0]);
    float left  = sp[row * SROW + ((c0 == 0)      ? 0      : c0 - 1)];
    float right = sp[row * SROW + ((c0 + 4 >= PS) ? PS - 1 : c0 + 4)];
    float4 gkv = *reinterpret_cast<const float4*>(gk + row * PS + c0);

    float cx[4] = {v.x,  v.y,  v.z,  v.w};
    float uu[4] = {up.x, up.y, up.z, up.w};
    float dd[4] = {dn.x, dn.y, dn.z, dn.w};
    float gg[4] = {gkv.x, gkv.y, gkv.z, gkv.w};
    float lf[4] = {left,  cx[0], cx[1], cx[2]};
    float rg[4] = {cx[1], cx[2], cx[3], right};

    const float TWOPI_F = 6.28318530717958647692f;  // rounds to 2*pi in fp32

    #pragma unroll
    for (int j = 0; j < 4; j++) {
        // gx = 0.5*l - 0.5*r  ==  0.5*fl(l-r)  (exact under any fma grouping)
        float gx = __fmul_rn(0.5f, __fadd_rn(lf[j], -rg[j]));
        float gy = __fmul_rn(0.5f, __fadd_rn(uu[j], -dd[j]));

        // s = (gx*gx + gy*gy) + 1e-10, left-to-right, no fma
        float s  = __fadd_rn(__fadd_rn(__fmul_rn(gx, gx), __fmul_rn(gy, gy)),
                             1e-10f);
        float mag = __fmul_rn(__fsqrt_rn(s), gg[j]);

        if (mag > 0.001f) {
            // ang = atan2f(gy, gx): same libdevice __nv_atan2f the reference hits
            float ang = atan2f(gy, gx);

            // m = jnp.mod(ang, 2pi_f):  rem==ang for |ang|<2pi; adjust if ang<0
            float m = (ang < 0.0f) ? __fadd_rn(ang, TWOPI_F) : ang;

            // o = fl(fl(36*m) / 2pi_f)
            float o = __fdiv_rn(__fmul_rn(36.0f, m), TWOPI_F);

            float bf = floorf(o);
            float w1 = __fsub_rn(o, bf);
            int ib = (int)bf;
            if (ib >= NBINS) ib -= NBINS;   // mod(floor, 36) for o==36 edge
            if (ib < 0) ib = 0;             // safety (shouldn't happen)

            // w = (1 - w1) * mag, no fma
            float w = __fmul_rn(__fsub_rn(1.0f, w1), mag);
            atomicAdd(&hist[ib], w);
        }
    }
    __syncthreads();

    // ---- hist / 1024 (exact), zero-padded conv1d k=3, fma-chain form ----
    if (t < NBINS) {
        float w0 = __ldg(smooth_w + 0);
        float w1 = __ldg(smooth_w + 1);
        float w2 = __ldg(smooth_w + 2);
        const float inv = 1.0f / 1024.0f;   // exact power-of-2 scale
        float hm = (t == 0)         ? 0.0f : __fmul_rn(hist[t - 1], inv);
        float h0 = __fmul_rn(hist[t], inv);
        float hp = (t == NBINS - 1) ? 0.0f : __fmul_rn(hist[t + 1], inv);
        smv[t] = __fmaf_rn(w2, hp, __fmaf_rn(w1, h0, __fmul_rn(w0, hm)));
    }
    __syncthreads();

    // ---- argmax (first index wins) + angle, replicating fp32 rounding ----
    if (t == 0) {
        float best = smv[0];
        int   bi   = 0;
        #pragma unroll
        for (int i = 1; i < NBINS; i++) {
            float vv = smv[i];
            if (vv > best) { best = vv; bi = i; }
        }
        const float TWOPI_Fc = 6.28318530717958647692f;
        const float PI_F     = 3.14159265358979323846f;
        float fi = (float)bi;
        float t1 = __fmul_rn(TWOPI_Fc, fi);
        float t2 = __fdiv_rn(t1, 36.0f);
        float t3 = __fsub_rn(t2, PI_F);
        out[b] = -t3;
    }
}

extern "C" void kernel_launch(void* const* d_in, const int* in_sizes, int n_in,
                              void* d_out, int out_size)
{
    const float* x        = (const float*)d_in[0];
    // d_in[1] = gx_w (0.5,0,-0.5), d_in[2] = gy_w (0.5,0,-0.5): folded in
    const float* smooth_w = (const float*)d_in[3];
    const float* gk       = (const float*)d_in[4];
    float* out = (float*)d_out;

    int B = in_sizes[0] / (PS * PS);
    orientation_kernel<<<B, 256>>>(x, smooth_w, gk, out);
}

// round 7
// speedup vs baseline: 1.0178x; 1.0178x over previous
#include <cuda_runtime.h>
#include <cuda_bf16.h>

#define NBINS 36
#define PS    32
#define SROW  36   // padded smem row stride (16B-aligned rows, conflict shift)

__global__ __launch_bounds__(256, 8)
void orientation_kernel(const float* __restrict__ x,
                        const float* __restrict__ smooth_w,
                        const float* __restrict__ gk,
                        float* __restrict__ out)
{
    __shared__ __align__(16) float sp[PS * SROW];
    __shared__ float hist[NBINS];
    __shared__ float smv[NBINS];

    const int t = threadIdx.x;
    const int b = blockIdx.x;

    // ---- stage patch: 1 LDG.128 + 1 STS.128 per thread ----
    const float4* xv = reinterpret_cast<const float4*>(x + (size_t)b * (PS * PS));
    float4 v = xv[t];
    const int row = t >> 3;           // 0..31
    const int c0  = (t & 7) * 4;      // 0,4,...,28

    // hoist smoothing weights early (hides LDG latency behind compute)
    float sw0 = 0.f, sw1 = 0.f, sw2 = 0.f;
    if (t < NBINS) {
        sw0 = __ldg(smooth_w + 0);
        sw1 = __ldg(smooth_w + 1);
        sw2 = __ldg(smooth_w + 2);
        hist[t] = 0.0f;
    }
    *reinterpret_cast<float4*>(&sp[row * SROW + c0]) = v;
    __syncthreads();

    // ---- replicate-padded neighbors ----
    const int rup = (row == 0)      ? 0      : row - 1;
    const int rdn = (row == PS - 1) ? PS - 1 : row + 1;
    float4 up = *reinterpret_cast<const float4*>(&sp[rup * SROW + c0]);
    float4 dn = *reinterpret_cast<const float4*>(&sp[rdn * SROW + c0]);
    float left  = sp[row * SROW + ((c0 == 0)      ? 0      : c0 - 1)];
    float right = sp[row * SROW + ((c0 + 4 >= PS) ? PS - 1 : c0 + 4)];
    float4 gkv = *reinterpret_cast<const float4*>(gk + row * PS + c0);

    float cx[4] = {v.x,  v.y,  v.z,  v.w};
    float uu[4] = {up.x, up.y, up.z, up.w};
    float dd[4] = {dn.x, dn.y, dn.z, dn.w};
    float gg[4] = {gkv.x, gkv.y, gkv.z, gkv.w};
    float lf[4] = {left,  cx[0], cx[1], cx[2]};
    float rg[4] = {cx[1], cx[2], cx[3], right};

    const float TWOPI_F = 6.28318530717958647692f;        // fp32(2*pi)
    const float RTWOPI  = 1.0f / 6.28318530717958647692f; // RN(1/C), compile-time

    #pragma unroll
    for (int j = 0; j < 4; j++) {
        // gx = 0.5*l - 0.5*r  ==  0.5*fl(l-r) bitwise (any fma grouping)
        float gx = __fmul_rn(0.5f, __fadd_rn(lf[j], -rg[j]));
        float gy = __fmul_rn(0.5f, __fadd_rn(uu[j], -dd[j]));

        // s = (gx*gx + gy*gy) + 1e-10, left-to-right, no fma
        float s  = __fadd_rn(__fadd_rn(__fmul_rn(gx, gx), __fmul_rn(gy, gy)),
                             1e-10f);
        float mag = __fmul_rn(__fsqrt_rn(s), gg[j]);

        // unconditional: whole warp executes this path anyway; predicate only
        // the atomic. atan2f == libdevice __nv_atan2f, matching the reference.
        float ang = atan2f(gy, gx);

        // m = jnp.mod(ang, 2pi_f): rem==ang for |ang|<2pi; adjust if negative
        float m = (ang < 0.0f) ? __fadd_rn(ang, TWOPI_F) : ang;

        // o = fl(fl(36*m) / 2pi_f) via constant-divisor Markstein division
        // (RN reciprocal + two exact-residual FMA refinements == div.rn.f32)
        float tnum = __fmul_rn(36.0f, m);
        float q0 = __fmul_rn(tnum, RTWOPI);
        float r0 = __fmaf_rn(-TWOPI_F, q0, tnum);
        float q1 = __fmaf_rn(r0, RTWOPI, q0);
        float r1 = __fmaf_rn(-TWOPI_F, q1, tnum);
        float o  = __fmaf_rn(r1, RTWOPI, q1);

        float bf = floorf(o);
        float w1 = __fsub_rn(o, bf);        // exact (Sterbenz)
        int ib = (int)bf;
        if (ib >= NBINS) ib -= NBINS;       // o == 36.0 edge -> bin 0

        float w = __fmul_rn(__fsub_rn(1.0f, w1), mag);
        if (mag > 0.001f)
            atomicAdd(&hist[ib], w);
    }
    __syncthreads();

    // ---- hist / 1024 (exact pow2), zero-padded conv1d k=3 ----
    if (t < NBINS) {
        const float inv = 1.0f / 1024.0f;
        float hm = (t == 0)         ? 0.0f : __fmul_rn(hist[t - 1], inv);
        float h0 = __fmul_rn(hist[t], inv);
        float hp = (t == NBINS - 1) ? 0.0f : __fmul_rn(hist[t + 1], inv);
        smv[t] = __fmaf_rn(sw2, hp, __fmaf_rn(sw1, h0, __fmul_rn(sw0, hm)));
    }
    __syncthreads();

    // ---- argmax (first index wins) + angle, fp32 rounding replica ----
    if (t == 0) {
        float best = smv[0];
        int   bi   = 0;
        #pragma unroll
        for (int i = 1; i < NBINS; i++) {
            float vv = smv[i];
            if (vv > best) { best = vv; bi = i; }
        }
        const float TWOPI_Fc = 6.28318530717958647692f;
        const float PI_F     = 3.14159265358979323846f;
        float t1 = __fmul_rn(TWOPI_Fc, (float)bi);
        float t2 = __fdiv_rn(t1, 36.0f);
        out[b] = -__fsub_rn(t2, PI_F);
    }
}

extern "C" void kernel_launch(void* const* d_in, const int* in_sizes, int n_in,
                              void* d_out, int out_size)
{
    const float* x        = (const float*)d_in[0];
    // d_in[1] = gx_w (0.5,0,-0.5), d_in[2] = gy_w (0.5,0,-0.5): folded in
    const float* smooth_w = (const float*)d_in[3];
    const float* gk       = (const float*)d_in[4];
    float* out = (float*)d_out;

    int B = in_sizes[0] / (PS * PS);
    orientation_kernel<<<B, 256>>>(x, smooth_w, gk, out);
}